// round 13
// baseline (speedup 1.0000x reference)
#include <cuda_runtime.h>
#include <cuda_fp16.h>
#include <math.h>
#include <stdint.h>

// Problem constants: B=4, N=4096, C=1024, H=16, D=64
#define BATCH 4
#define SEQ   4096
#define CH    1024
#define HEADS 16
#define HD    64
#define ROWS  (BATCH*SEQ)        // 16384
#define QKVC  (3*CH)             // 3072
#define BH    (BATCH*HEADS)      // 64
#define KVCHUNKS 8
#define QSC   65536.0f           // q~tilde scaling (avoids fp16 subnormals)

// ---------------- scratch (device globals: allocation-free) ----------------
__device__ __align__(256) __half g_qkvh  [(size_t)ROWS * QKVC];  // qkv fp16 (elu+1 on q,k)
__device__ __align__(256) __half g_xh    [(size_t)ROWS * CH];
__device__ __align__(256) __half g_wqkvh [(size_t)CH * QKVC];
__device__ __align__(256) __half g_wprojh[(size_t)CH * CH];
__device__ __align__(256) __half g_qt    [(size_t)ROWS * CH];    // scaled q~ (fp16)
__device__ __align__(256) __half g_kvh   [(size_t)BH * HD * HD];
__device__ __align__(256) __half g_Mh    [(size_t)BATCH * CH * CH]; // per-batch M = kv @ wproj
__device__ float g_sumk [(size_t)BH * HD];
__device__ float g_kvp  [(size_t)KVCHUNKS * BH * HD * HD];
__device__ float g_sumkp[(size_t)KVCHUNKS * BH * HD];

__device__ __forceinline__ uint32_t smem_u32(const void* p) {
    uint32_t a;
    asm("{ .reg .u64 t; cvta.to.shared.u64 t, %1; cvt.u32.u64 %0, t; }" : "=r"(a) : "l"(p));
    return a;
}

#define MMA16816(acc, af, b0, b1)                                              \
    asm volatile(                                                              \
        "mma.sync.aligned.m16n8k16.row.col.f32.f16.f16.f32 "                   \
        "{%0,%1,%2,%3}, {%4,%5,%6,%7}, {%8,%9}, {%0,%1,%2,%3};\n"              \
        : "+f"((acc)[0]), "+f"((acc)[1]), "+f"((acc)[2]), "+f"((acc)[3])       \
        : "r"((af)[0]), "r"((af)[1]), "r"((af)[2]), "r"((af)[3]),              \
          "r"(b0), "r"(b1))

// ===== fp16 GEMM: 128 threads = 4 warps (2x2), warp tile 64x64, =====
// ===== cp.async 3-stage, 2 CTAs/SM.  Block 128x128, BK=64.        =====
// MODE 1: elu+1 on cols < 2048, fp16 out.  MODE 2: *2^-16 + bias, fp32 out,
//         B pointer advanced per batch (blockIdx.y >> 5).
#define BKH 64
#define NST 3
#define STAGE_A (128 * BKH * 2)
#define STAGE_B (BKH * 128 * 2)
#define STAGE_SZ (STAGE_A + STAGE_B)
#define HG_SMEM (NST * STAGE_SZ)           // 98304 B

template <int MODE>
__global__ __launch_bounds__(128, 2)
void hgemm(const __half* __restrict__ A, const __half* __restrict__ B,
           const float* __restrict__ bias, void* __restrict__ Cv,
           int Ncols, int K)
{
    extern __shared__ __align__(16) char smem[];
    const uint32_t sb = smem_u32(smem);

    const int tid   = threadIdx.x;
    const int lane  = tid & 31;
    const int warp  = tid >> 5;
    const int warpM = warp >> 1;
    const int warpN = warp & 1;
    const int g     = lane >> 2;
    const int tig   = lane & 3;

    const __half* Aptr = A + (size_t)blockIdx.y * 128 * K;
    const __half* Bptr = B + (size_t)blockIdx.x * 128;
    if (MODE == 2) Bptr += (size_t)(blockIdx.y >> 5) * CH * CH;  // per-batch M

    float acc[4][8][4];
    #pragma unroll
    for (int i = 0; i < 4; i++)
        #pragma unroll
        for (int j = 0; j < 8; j++)
            #pragma unroll
            for (int l = 0; l < 4; l++) acc[i][j][l] = 0.f;

    auto issue = [&](int kt, int s) {
        const uint32_t aB = sb + s * STAGE_SZ;
        const uint32_t bB = aB + STAGE_A;
        #pragma unroll
        for (int it = 0; it < 8; it++) {
            int id = tid + it * 128;
            int r = id >> 3, c = id & 7;
            uint32_t dst = aB + r * 128 + ((c ^ (r & 7)) << 4);
            const __half* src = Aptr + (size_t)r * K + kt * BKH + c * 8;
            asm volatile("cp.async.cg.shared.global [%0], [%1], 16;" :: "r"(dst), "l"(src));
        }
        #pragma unroll
        for (int it = 0; it < 8; it++) {
            int id = tid + it * 128;
            int kr = id >> 4, c = id & 15;
            uint32_t dst = bB + kr * 256 + ((c ^ (kr & 7)) << 4);
            const __half* src = Bptr + (size_t)(kt * BKH + kr) * Ncols + c * 8;
            asm volatile("cp.async.cg.shared.global [%0], [%1], 16;" :: "r"(dst), "l"(src));
        }
    };

    auto compute = [&](int s) {
        const uint32_t a_base = sb + s * STAGE_SZ;
        const uint32_t b_base = a_base + STAGE_A;
        #pragma unroll
        for (int ks = 0; ks < 4; ks++) {
            uint32_t af[4][4], bf[8][2];
            #pragma unroll
            for (int mi = 0; mi < 4; mi++) {
                int r = warpM * 64 + mi * 16 + (lane & 15);
                int k = ks * 16 + ((lane >> 4) << 3);
                int c = k >> 3;
                uint32_t addr = a_base + r * 128 + ((c ^ (r & 7)) << 4);
                asm volatile(
                    "ldmatrix.sync.aligned.m8n8.x4.shared.b16 {%0,%1,%2,%3}, [%4];"
                    : "=r"(af[mi][0]), "=r"(af[mi][1]), "=r"(af[mi][2]), "=r"(af[mi][3])
                    : "r"(addr));
            }
            #pragma unroll
            for (int nip = 0; nip < 4; nip++) {
                int k = ks * 16 + (lane & 15);
                int n = warpN * 64 + nip * 16 + ((lane >> 4) << 3);
                int c = n >> 3;
                uint32_t addr = b_base + k * 256 + ((c ^ (k & 7)) << 4);
                asm volatile(
                    "ldmatrix.sync.aligned.m8n8.x4.trans.shared.b16 {%0,%1,%2,%3}, [%4];"
                    : "=r"(bf[2 * nip][0]), "=r"(bf[2 * nip][1]),
                      "=r"(bf[2 * nip + 1][0]), "=r"(bf[2 * nip + 1][1])
                    : "r"(addr));
            }
            #pragma unroll
            for (int mi = 0; mi < 4; mi++)
                #pragma unroll
                for (int ni = 0; ni < 8; ni++)
                    MMA16816(acc[mi][ni], af[mi], bf[ni][0], bf[ni][1]);
        }
    };

    const int nTiles = K / BKH;

    #pragma unroll
    for (int s = 0; s < NST - 1; s++) {
        issue(s, s);
        asm volatile("cp.async.commit_group;" ::: "memory");
    }

    for (int t = 0; t < nTiles; t++) {
        asm volatile("cp.async.wait_group %0;" :: "n"(NST - 2) : "memory");
        __syncthreads();
        const int nt = t + NST - 1;
        if (nt < nTiles) issue(nt, nt % NST);
        asm volatile("cp.async.commit_group;" ::: "memory");
        compute(t % NST);
    }

    #pragma unroll
    for (int mi = 0; mi < 4; mi++) {
        #pragma unroll
        for (int ni = 0; ni < 8; ni++) {
            const int r0 = blockIdx.y * 128 + warpM * 64 + mi * 16 + g;
            const int c0 = blockIdx.x * 128 + warpN * 64 + ni * 8 + 2 * tig;
            #pragma unroll
            for (int hh = 0; hh < 2; hh++) {
                float v0 = acc[mi][ni][hh * 2 + 0];
                float v1 = acc[mi][ni][hh * 2 + 1];
                if (MODE == 1) {
                    if (c0 < 2 * CH)     v0 = (v0 > 0.f) ? (v0 + 1.f) : expf(v0);
                    if (c0 + 1 < 2 * CH) v1 = (v1 > 0.f) ? (v1 + 1.f) : expf(v1);
                    __half2 p = __floats2half2_rn(v0, v1);
                    *(__half2*)((__half*)Cv + (size_t)(r0 + hh * 8) * Ncols + c0) = p;
                } else {
                    v0 = v0 * (1.0f / QSC) + bias[c0];
                    v1 = v1 * (1.0f / QSC) + bias[c0 + 1];
                    *(float2*)((float*)Cv + (size_t)(r0 + hh * 8) * Ncols + c0) =
                        make_float2(v0, v1);
                }
            }
        }
    }
}

// ================= fused prep: fp32 -> fp16 (rn) for x, w_qkv, w_proj ======
#define N8X (ROWS * CH / 8)
#define N8W (CH * QKVC / 8)
#define N8P (CH * CH / 8)
__global__ __launch_bounds__(256)
void cvt_all_kernel(const float4* __restrict__ x, const float4* __restrict__ wq,
                    const float4* __restrict__ wp)
{
    int i = blockIdx.x * 256 + threadIdx.x;
    const float4* in;
    uint4* outp;
    int j;
    if (i < N8X)            { in = x;  outp = (uint4*)g_xh;     j = i; }
    else if (i < N8X + N8W) { in = wq; outp = (uint4*)g_wqkvh;  j = i - N8X; }
    else                    { in = wp; outp = (uint4*)g_wprojh; j = i - N8X - N8W; }
    float4 a = in[2 * j], b = in[2 * j + 1];
    __half2 h0 = __floats2half2_rn(a.x, a.y);
    __half2 h1 = __floats2half2_rn(a.z, a.w);
    __half2 h2 = __floats2half2_rn(b.x, b.y);
    __half2 h3 = __floats2half2_rn(b.z, b.w);
    uint4 o;
    o.x = *reinterpret_cast<uint32_t*>(&h0);
    o.y = *reinterpret_cast<uint32_t*>(&h1);
    o.z = *reinterpret_cast<uint32_t*>(&h2);
    o.w = *reinterpret_cast<uint32_t*>(&h3);
    outp[j] = o;
}

// ===== kv via tensor cores: kv[d,e] = sum_n k[n,d] v[n,e]; + sumk ==========
__global__ __launch_bounds__(128)
void kv_mma_kernel()
{
    __shared__ __align__(16) __half ks[32 * 64];
    __shared__ __align__(16) __half vs[32 * 64];
    __shared__ float red[2][64];

    const int tid  = threadIdx.x;
    const int lane = tid & 31;
    const int warp = tid >> 5;
    const int bh   = blockIdx.x;
    const int chunk = blockIdx.y;
    const int b = bh / HEADS, h = bh % HEADS;

    const __half* base = g_qkvh + (size_t)b * SEQ * QKVC + h * HD;
    const int nBeg = chunk * (SEQ / KVCHUNKS);
    const int nEnd = nBeg + (SEQ / KVCHUNKS);

    const uint32_t kb = smem_u32(ks);
    const uint32_t vb = smem_u32(vs);

    float acc[8][4];
    #pragma unroll
    for (int j = 0; j < 8; j++)
        #pragma unroll
        for (int l = 0; l < 4; l++) acc[j][l] = 0.f;

    const int scol = tid & 63;
    const int srow0 = (tid >> 6) * 16;
    float ssum = 0.f;
    const int s_in = (scol & 7) * 2;

    const int d0 = warp * 16;
    const int a_nrow = (lane & 7) + ((lane >> 4) << 3);
    const int a_dcol = d0 + (lane & 8);
    const int a_chunk = a_dcol >> 3;

    const int b_krow = lane & 15;
    const int b_eoff = (lane >> 4) << 3;

    for (int n0 = nBeg; n0 < nEnd; n0 += 32) {
        #pragma unroll
        for (int it = 0; it < 2; it++) {
            int id = tid + it * 128;
            int r = id >> 3, c = id & 7;
            const __half* rowp = base + (size_t)(n0 + r) * QKVC;
            uint4 kq = *(const uint4*)(rowp + CH + c * 8);
            uint4 vq = *(const uint4*)(rowp + 2 * CH + c * 8);
            *(uint4*)((char*)ks + r * 128 + ((c ^ (r & 7)) << 4)) = kq;
            *(uint4*)((char*)vs + r * 128 + ((c ^ (r & 7)) << 4)) = vq;
        }
        __syncthreads();

        #pragma unroll
        for (int ksi = 0; ksi < 2; ksi++) {
            uint32_t af[4], bf[8][2];
            {
                int nr = ksi * 16 + a_nrow;
                uint32_t addr = kb + nr * 128 + (((a_chunk ^ (nr & 7))) << 4);
                asm volatile(
                    "ldmatrix.sync.aligned.m8n8.x4.trans.shared.b16 {%0,%1,%2,%3}, [%4];"
                    : "=r"(af[0]), "=r"(af[1]), "=r"(af[2]), "=r"(af[3])
                    : "r"(addr));
            }
            #pragma unroll
            for (int nip = 0; nip < 4; nip++) {
                int kk = ksi * 16 + b_krow;
                int e = nip * 16 + b_eoff;
                int c = e >> 3;
                uint32_t addr = vb + kk * 128 + (((c ^ (kk & 7))) << 4);
                asm volatile(
                    "ldmatrix.sync.aligned.m8n8.x4.trans.shared.b16 {%0,%1,%2,%3}, [%4];"
                    : "=r"(bf[2 * nip][0]), "=r"(bf[2 * nip][1]),
                      "=r"(bf[2 * nip + 1][0]), "=r"(bf[2 * nip + 1][1])
                    : "r"(addr));
            }
            #pragma unroll
            for (int ni = 0; ni < 8; ni++)
                MMA16816(acc[ni], af, bf[ni][0], bf[ni][1]);
        }

        #pragma unroll
        for (int rr = 0; rr < 16; rr++) {
            int row = srow0 + rr;
            uint32_t a = kb + row * 128 + ((((scol >> 3) ^ (row & 7))) << 4) + s_in;
            __half hv;
            asm volatile("ld.shared.b16 %0, [%1];" : "=h"(*(short*)&hv) : "r"(a));
            ssum += __half2float(hv);
        }
        __syncthreads();
    }

    const int g = lane >> 2, tig = lane & 3;
    float* kvp = g_kvp + ((size_t)chunk * BH + bh) * HD * HD;
    #pragma unroll
    for (int hh = 0; hh < 2; hh++) {
        const int dr = d0 + g + hh * 8;
        #pragma unroll
        for (int ni = 0; ni < 8; ni++) {
            const int e = ni * 8 + 2 * tig;
            *(float2*)(kvp + dr * HD + e) =
                make_float2(acc[ni][hh * 2 + 0], acc[ni][hh * 2 + 1]);
        }
    }
    red[tid >> 6][scol] = ssum;
    __syncthreads();
    if (tid < HD)
        g_sumkp[((size_t)chunk * BH + bh) * HD + tid] = red[0][tid] + red[1][tid];
}

__global__ __launch_bounds__(256)
void kv_reduce_kernel()
{
    const int bh = blockIdx.x;
    const int tid = threadIdx.x;
    for (int i = tid; i < HD * HD; i += 256) {
        float s = 0.f;
        #pragma unroll
        for (int c = 0; c < KVCHUNKS; c++)
            s += g_kvp[((size_t)c * BH + bh) * HD * HD + i];
        g_kvh[(size_t)bh * HD * HD + i] = __float2half_rn(s);
    }
    if (tid < HD) {
        float s = 0.f;
        #pragma unroll
        for (int c = 0; c < KVCHUNKS; c++)
            s += g_sumkp[((size_t)c * BH + bh) * HD + tid];
        g_sumk[(size_t)bh * HD + tid] = s;
    }
}

// ===== q~ = q * (QSC / (q . sumk)) per (row, head), fp16 out ===============
__global__ __launch_bounds__(256)
void qscale_kernel()
{
    const int idx = blockIdx.x * 256 + threadIdx.x;   // ROWS*HEADS threads
    const int n = idx >> 4;
    const int h = idx & 15;
    const int b = n >> 12;

    const __half* qr = g_qkvh + (size_t)n * QKVC + h * HD;
    const float*  sk = g_sumk + ((size_t)b * HEADS + h) * HD;

    uint4 v[8];
    float denom = 0.f;
    #pragma unroll
    for (int i = 0; i < 8; i++) {
        v[i] = ((const uint4*)qr)[i];
        const __half2* hp = (const __half2*)&v[i];
        #pragma unroll
        for (int j = 0; j < 4; j++) {
            float2 f = __half22float2(hp[j]);
            denom += f.x * sk[i * 8 + 2 * j] + f.y * sk[i * 8 + 2 * j + 1];
        }
    }
    const float s = QSC / denom;

    __half* outp = g_qt + (size_t)n * CH + h * HD;
    #pragma unroll
    for (int i = 0; i < 8; i++) {
        const __half2* hp = (const __half2*)&v[i];
        uint4 o;
        uint32_t* op = (uint32_t*)&o;
        #pragma unroll
        for (int j = 0; j < 4; j++) {
            float2 f = __half22float2(hp[j]);
            __half2 p = __floats2half2_rn(f.x * s, f.y * s);
            op[j] = *reinterpret_cast<uint32_t*>(&p);
        }
        ((uint4*)outp)[i] = o;
    }
}

// ===== M_{b} rows h*64+d = kv_{b,h} @ wproj[h*64: , :] (fp16 out) ==========
// grid (BH, CH/128), 128 threads = 4 warps; per block M=64(d) N=128 K=64(e).
__global__ __launch_bounds__(128)
void mproj_kernel()
{
    __shared__ __align__(16) __half kvs[64 * 64];    // [d][e] swizzled, 8KB
    __shared__ __align__(16) __half ws[64 * 128];    // [e][c] swizzled, 16KB

    const int tid  = threadIdx.x;
    const int lane = tid & 31;
    const int warp = tid >> 5;
    const int bh   = blockIdx.x;
    const int jn   = blockIdx.y;          // 128-col tile of CH
    const int b = bh / HEADS, h = bh % HEADS;

    // load kv (64x64): 512 chunks, 4/thread
    const __half* kvg = g_kvh + (size_t)bh * HD * HD;
    #pragma unroll
    for (int it = 0; it < 4; it++) {
        int id = tid + it * 128;
        int r = id >> 3, c = id & 7;
        uint4 o = *(const uint4*)(kvg + r * HD + c * 8);
        *(uint4*)((char*)kvs + r * 128 + ((c ^ (r & 7)) << 4)) = o;
    }
    // load w slice (64x128): 1024 chunks, 8/thread
    const __half* wg = g_wprojh + (size_t)(h * HD) * CH + jn * 128;
    #pragma unroll
    for (int it = 0; it < 8; it++) {
        int id = tid + it * 128;
        int e = id >> 4, c = id & 15;
        uint4 o = *(const uint4*)(wg + (size_t)e * CH + c * 8);
        *(uint4*)((char*)ws + e * 256 + ((c ^ (e & 7)) << 4)) = o;
    }
    __syncthreads();

    const uint32_t kb = smem_u32(kvs);
    const uint32_t wb = smem_u32(ws);

    float acc[4][4][4];
    #pragma unroll
    for (int i = 0; i < 4; i++)
        #pragma unroll
        for (int j = 0; j < 4; j++)
            #pragma unroll
            for (int l = 0; l < 4; l++) acc[i][j][l] = 0.f;

    #pragma unroll
    for (int ksi = 0; ksi < 4; ksi++) {
        uint32_t af[4][4], bf[4][2];
        #pragma unroll
        for (int mi = 0; mi < 4; mi++) {
            int r = mi * 16 + (lane & 15);
            int k = ksi * 16 + ((lane >> 4) << 3);
            int c = k >> 3;
            uint32_t addr = kb + r * 128 + ((c ^ (r & 7)) << 4);
            asm volatile(
                "ldmatrix.sync.aligned.m8n8.x4.shared.b16 {%0,%1,%2,%3}, [%4];"
                : "=r"(af[mi][0]), "=r"(af[mi][1]), "=r"(af[mi][2]), "=r"(af[mi][3])
                : "r"(addr));
        }
        #pragma unroll
        for (int nip = 0; nip < 2; nip++) {
            int k = ksi * 16 + (lane & 15);
            int n = warp * 32 + nip * 16 + ((lane >> 4) << 3);
            int c = n >> 3;
            uint32_t addr = wb + k * 256 + ((c ^ (k & 7)) << 4);
            asm volatile(
                "ldmatrix.sync.aligned.m8n8.x4.trans.shared.b16 {%0,%1,%2,%3}, [%4];"
                : "=r"(bf[2 * nip][0]), "=r"(bf[2 * nip][1]),
                  "=r"(bf[2 * nip + 1][0]), "=r"(bf[2 * nip + 1][1])
                : "r"(addr));
        }
        #pragma unroll
        for (int mi = 0; mi < 4; mi++)
            #pragma unroll
            for (int ni = 0; ni < 4; ni++)
                MMA16816(acc[mi][ni], af[mi], bf[ni][0], bf[ni][1]);
    }

    const int g = lane >> 2, tig = lane & 3;
    __half* Mb = g_Mh + (size_t)b * CH * CH;
    #pragma unroll
    for (int mi = 0; mi < 4; mi++) {
        #pragma unroll
        for (int hh = 0; hh < 2; hh++) {
            const int d = mi * 16 + g + hh * 8;
            #pragma unroll
            for (int ni = 0; ni < 4; ni++) {
                const int c0 = jn * 128 + warp * 32 + ni * 8 + 2 * tig;
                __half2 p = __floats2half2_rn(acc[mi][ni][hh * 2 + 0],
                                              acc[mi][ni][hh * 2 + 1]);
                *(__half2*)(Mb + (size_t)(h * HD + d) * CH + c0) = p;
            }
        }
    }
}

// ---------------------------------------------------------------------------
extern "C" void kernel_launch(void* const* d_in, const int* in_sizes, int n_in,
                              void* d_out, int out_size)
{
    const float* x      = (const float*)d_in[0];
    const float* w_qkv  = (const float*)d_in[1];
    const float* w_proj = (const float*)d_in[2];
    const float* b_proj = (const float*)d_in[3];
    float* out = (float*)d_out;

    __half *qkvh_p, *xh_p, *wqkvh_p, *qt_p, *Mh_p;
    cudaGetSymbolAddress((void**)&qkvh_p, g_qkvh);
    cudaGetSymbolAddress((void**)&xh_p,   g_xh);
    cudaGetSymbolAddress((void**)&wqkvh_p,g_wqkvh);
    cudaGetSymbolAddress((void**)&qt_p,   g_qt);
    cudaGetSymbolAddress((void**)&Mh_p,   g_Mh);

    cudaFuncSetAttribute(hgemm<1>, cudaFuncAttributeMaxDynamicSharedMemorySize, HG_SMEM);
    cudaFuncSetAttribute(hgemm<2>, cudaFuncAttributeMaxDynamicSharedMemorySize, HG_SMEM);

    // 0) fused fp32 -> fp16 conversion for x, w_qkv, w_proj
    cvt_all_kernel<<<(N8X + N8W + N8P) / 256, 256>>>(
        (const float4*)x, (const float4*)w_qkv, (const float4*)w_proj);

    // 1) qkv = x @ w_qkv (fp16 TC), elu+1 fused, fp16 out
    {
        dim3 grid(QKVC / 128, ROWS / 128);
        hgemm<1><<<grid, 128, HG_SMEM>>>(xh_p, wqkvh_p, nullptr, qkvh_p, QKVC, CH);
    }
    // 2) kv outer product on tensor cores (seq-split) + reduce
    {
        dim3 grid(BH, KVCHUNKS);
        kv_mma_kernel<<<grid, 128>>>();
        kv_reduce_kernel<<<BH, 256>>>();
    }
    // 3a) q~ = q * (QSC / (q . sumk))
    qscale_kernel<<<ROWS * HEADS / 256, 256>>>();
    // 3b) M_b = stack_h(kv_{b,h} @ wproj_h)
    {
        dim3 grid(BH, CH / 128);
        mproj_kernel<<<grid, 128>>>();
    }
    // 4) out = q~ @ M_b * 2^-16 + bias (fp16 TC, fp32 out)
    {
        dim3 grid(CH / 128, ROWS / 128);
        hgemm<2><<<grid, 128, HG_SMEM>>>(qt_p, Mh_p, b_proj, out, CH, CH);
    }
}

// round 14
// speedup vs baseline: 1.0476x; 1.0476x over previous
#include <cuda_runtime.h>
#include <cuda_fp16.h>
#include <math.h>
#include <stdint.h>

// Problem constants: B=4, N=4096, C=1024, H=16, D=64
#define BATCH 4
#define SEQ   4096
#define CH    1024
#define HEADS 16
#define HD    64
#define ROWS  (BATCH*SEQ)        // 16384
#define QKVC  (3*CH)             // 3072
#define BH    (BATCH*HEADS)      // 64
#define KVCHUNKS 8

// ---------------- scratch (device globals: allocation-free) ----------------
__device__ __align__(256) __half g_qkvh  [(size_t)ROWS * QKVC];  // qkv fp16 (elu+1 on q,k)
__device__ __align__(256) __half g_xh    [(size_t)ROWS * CH];
__device__ __align__(256) __half g_wqkvh [(size_t)CH * QKVC];
__device__ __align__(256) __half g_wprojh[(size_t)CH * CH];
__device__ __align__(256) __half g_yh    [(size_t)ROWS * CH];
__device__ __align__(256) __half g_kvh   [(size_t)BH * HD * HD];
__device__ float g_sumk [(size_t)BH * HD];
__device__ float g_kvp  [(size_t)KVCHUNKS * BH * HD * HD];
__device__ float g_sumkp[(size_t)KVCHUNKS * BH * HD];

__device__ __forceinline__ uint32_t smem_u32(const void* p) {
    uint32_t a;
    asm("{ .reg .u64 t; cvta.to.shared.u64 t, %1; cvt.u32.u64 %0, t; }" : "=r"(a) : "l"(p));
    return a;
}

// volatile variant — measured best inside hgemm (R11: 300.1us vs R12: 318.7us)
#define MMA16816_V(acc, af, b0, b1)                                            \
    asm volatile(                                                              \
        "mma.sync.aligned.m16n8k16.row.col.f32.f16.f16.f32 "                   \
        "{%0,%1,%2,%3}, {%4,%5,%6,%7}, {%8,%9}, {%0,%1,%2,%3};\n"              \
        : "+f"((acc)[0]), "+f"((acc)[1]), "+f"((acc)[2]), "+f"((acc)[3])       \
        : "r"((af)[0]), "r"((af)[1]), "r"((af)[2]), "r"((af)[3]),              \
          "r"(b0), "r"(b1))

// non-volatile variant — matches R12 codegen in kv_mma / y_mma (measured fine)
#define MMA16816(acc, af, b0, b1)                                              \
    asm("mma.sync.aligned.m16n8k16.row.col.f32.f16.f16.f32 "                   \
        "{%0,%1,%2,%3}, {%4,%5,%6,%7}, {%8,%9}, {%0,%1,%2,%3};\n"              \
        : "+f"((acc)[0]), "+f"((acc)[1]), "+f"((acc)[2]), "+f"((acc)[3])       \
        : "r"((af)[0]), "r"((af)[1]), "r"((af)[2]), "r"((af)[3]),              \
          "r"(b0), "r"(b1))

// ===== fp16 GEMM: 128 threads = 4 warps (2x2), warp tile 64x64, =====
// ===== cp.async 3-stage, 2 CTAs/SM.  Block 128x128, BK=64.        =====
#define BKH 64
#define NST 3
#define STAGE_A (128 * BKH * 2)
#define STAGE_B (BKH * 128 * 2)
#define STAGE_SZ (STAGE_A + STAGE_B)
#define HG_SMEM (NST * STAGE_SZ)           // 98304 B

template <int MODE>
__global__ __launch_bounds__(128, 2)
void hgemm(const __half* __restrict__ A, const __half* __restrict__ B,
           const float* __restrict__ bias, void* __restrict__ Cv,
           int Ncols, int K)
{
    extern __shared__ __align__(16) char smem[];
    const uint32_t sb = smem_u32(smem);

    const int tid   = threadIdx.x;
    const int lane  = tid & 31;
    const int warp  = tid >> 5;
    const int warpM = warp >> 1;
    const int warpN = warp & 1;
    const int g     = lane >> 2;
    const int tig   = lane & 3;

    const __half* Aptr = A + (size_t)blockIdx.y * 128 * K;
    const __half* Bptr = B + (size_t)blockIdx.x * 128;

    float acc[4][8][4];
    #pragma unroll
    for (int i = 0; i < 4; i++)
        #pragma unroll
        for (int j = 0; j < 8; j++)
            #pragma unroll
            for (int l = 0; l < 4; l++) acc[i][j][l] = 0.f;

    auto issue = [&](int kt, int s) {
        const uint32_t aB = sb + s * STAGE_SZ;
        const uint32_t bB = aB + STAGE_A;
        #pragma unroll
        for (int it = 0; it < 8; it++) {
            int id = tid + it * 128;
            int r = id >> 3, c = id & 7;
            uint32_t dst = aB + r * 128 + ((c ^ (r & 7)) << 4);
            const __half* src = Aptr + (size_t)r * K + kt * BKH + c * 8;
            asm volatile("cp.async.cg.shared.global [%0], [%1], 16;" :: "r"(dst), "l"(src));
        }
        #pragma unroll
        for (int it = 0; it < 8; it++) {
            int id = tid + it * 128;
            int kr = id >> 4, c = id & 15;
            uint32_t dst = bB + kr * 256 + ((c ^ (kr & 7)) << 4);
            const __half* src = Bptr + (size_t)(kt * BKH + kr) * Ncols + c * 8;
            asm volatile("cp.async.cg.shared.global [%0], [%1], 16;" :: "r"(dst), "l"(src));
        }
    };

    auto compute = [&](int s) {
        const uint32_t a_base = sb + s * STAGE_SZ;
        const uint32_t b_base = a_base + STAGE_A;
        #pragma unroll
        for (int ks = 0; ks < 4; ks++) {
            uint32_t af[4][4], bf[8][2];
            #pragma unroll
            for (int mi = 0; mi < 4; mi++) {
                int r = warpM * 64 + mi * 16 + (lane & 15);
                int k = ks * 16 + ((lane >> 4) << 3);
                int c = k >> 3;
                uint32_t addr = a_base + r * 128 + ((c ^ (r & 7)) << 4);
                asm volatile(
                    "ldmatrix.sync.aligned.m8n8.x4.shared.b16 {%0,%1,%2,%3}, [%4];"
                    : "=r"(af[mi][0]), "=r"(af[mi][1]), "=r"(af[mi][2]), "=r"(af[mi][3])
                    : "r"(addr));
            }
            #pragma unroll
            for (int nip = 0; nip < 4; nip++) {
                int k = ks * 16 + (lane & 15);
                int n = warpN * 64 + nip * 16 + ((lane >> 4) << 3);
                int c = n >> 3;
                uint32_t addr = b_base + k * 256 + ((c ^ (k & 7)) << 4);
                asm volatile(
                    "ldmatrix.sync.aligned.m8n8.x4.trans.shared.b16 {%0,%1,%2,%3}, [%4];"
                    : "=r"(bf[2 * nip][0]), "=r"(bf[2 * nip][1]),
                      "=r"(bf[2 * nip + 1][0]), "=r"(bf[2 * nip + 1][1])
                    : "r"(addr));
            }
            #pragma unroll
            for (int mi = 0; mi < 4; mi++)
                #pragma unroll
                for (int ni = 0; ni < 8; ni++)
                    MMA16816_V(acc[mi][ni], af[mi], bf[ni][0], bf[ni][1]);
        }
    };

    const int nTiles = K / BKH;

    #pragma unroll
    for (int s = 0; s < NST - 1; s++) {
        issue(s, s);
        asm volatile("cp.async.commit_group;" ::: "memory");
    }

    for (int t = 0; t < nTiles; t++) {
        asm volatile("cp.async.wait_group %0;" :: "n"(NST - 2) : "memory");
        __syncthreads();
        const int nt = t + NST - 1;
        if (nt < nTiles) issue(nt, nt % NST);
        asm volatile("cp.async.commit_group;" ::: "memory");
        compute(t % NST);
    }

    #pragma unroll
    for (int mi = 0; mi < 4; mi++) {
        #pragma unroll
        for (int ni = 0; ni < 8; ni++) {
            const int r0 = blockIdx.y * 128 + warpM * 64 + mi * 16 + g;
            const int c0 = blockIdx.x * 128 + warpN * 64 + ni * 8 + 2 * tig;
            #pragma unroll
            for (int hh = 0; hh < 2; hh++) {
                float v0 = acc[mi][ni][hh * 2 + 0];
                float v1 = acc[mi][ni][hh * 2 + 1];
                if (MODE == 1) {
                    if (c0 < 2 * CH)     v0 = (v0 > 0.f) ? (v0 + 1.f) : expf(v0);
                    if (c0 + 1 < 2 * CH) v1 = (v1 > 0.f) ? (v1 + 1.f) : expf(v1);
                    __half2 p = __floats2half2_rn(v0, v1);
                    *(__half2*)((__half*)Cv + (size_t)(r0 + hh * 8) * Ncols + c0) = p;
                } else {
                    v0 += bias[c0]; v1 += bias[c0 + 1];
                    *(float2*)((float*)Cv + (size_t)(r0 + hh * 8) * Ncols + c0) =
                        make_float2(v0, v1);
                }
            }
        }
    }
}

// ================= fused prep: fp32 -> fp16 (rn) for x, w_qkv, w_proj ======
#define N8X (ROWS * CH / 8)
#define N8W (CH * QKVC / 8)
#define N8P (CH * CH / 8)
__global__ __launch_bounds__(256)
void cvt_all_kernel(const float4* __restrict__ x, const float4* __restrict__ wq,
                    const float4* __restrict__ wp)
{
    int i = blockIdx.x * 256 + threadIdx.x;
    const float4* in;
    uint4* outp;
    int j;
    if (i < N8X)            { in = x;  outp = (uint4*)g_xh;     j = i; }
    else if (i < N8X + N8W) { in = wq; outp = (uint4*)g_wqkvh;  j = i - N8X; }
    else                    { in = wp; outp = (uint4*)g_wprojh; j = i - N8X - N8W; }
    float4 a = in[2 * j], b = in[2 * j + 1];
    __half2 h0 = __floats2half2_rn(a.x, a.y);
    __half2 h1 = __floats2half2_rn(a.z, a.w);
    __half2 h2 = __floats2half2_rn(b.x, b.y);
    __half2 h3 = __floats2half2_rn(b.z, b.w);
    uint4 o;
    o.x = *reinterpret_cast<uint32_t*>(&h0);
    o.y = *reinterpret_cast<uint32_t*>(&h1);
    o.z = *reinterpret_cast<uint32_t*>(&h2);
    o.w = *reinterpret_cast<uint32_t*>(&h3);
    outp[j] = o;
}

// ===== kv via tensor cores: kv[d,e] = sum_n k[n,d] v[n,e]; + sumk ==========
__global__ __launch_bounds__(128)
void kv_mma_kernel()
{
    __shared__ __align__(16) __half ks[32 * 64];
    __shared__ __align__(16) __half vs[32 * 64];
    __shared__ float red[2][64];

    const int tid  = threadIdx.x;
    const int lane = tid & 31;
    const int warp = tid >> 5;
    const int bh   = blockIdx.x;
    const int chunk = blockIdx.y;
    const int b = bh / HEADS, h = bh % HEADS;

    const __half* base = g_qkvh + (size_t)b * SEQ * QKVC + h * HD;
    const int nBeg = chunk * (SEQ / KVCHUNKS);
    const int nEnd = nBeg + (SEQ / KVCHUNKS);

    const uint32_t kb = smem_u32(ks);
    const uint32_t vb = smem_u32(vs);

    float acc[8][4];
    #pragma unroll
    for (int j = 0; j < 8; j++)
        #pragma unroll
        for (int l = 0; l < 4; l++) acc[j][l] = 0.f;

    const int scol = tid & 63;
    const int srow0 = (tid >> 6) * 16;
    float ssum = 0.f;
    const int s_in = (scol & 7) * 2;

    const int d0 = warp * 16;
    const int a_nrow = (lane & 7) + ((lane >> 4) << 3);
    const int a_dcol = d0 + (lane & 8);
    const int a_chunk = a_dcol >> 3;

    const int b_krow = lane & 15;
    const int b_eoff = (lane >> 4) << 3;

    for (int n0 = nBeg; n0 < nEnd; n0 += 32) {
        #pragma unroll
        for (int it = 0; it < 2; it++) {
            int id = tid + it * 128;
            int r = id >> 3, c = id & 7;
            const __half* rowp = base + (size_t)(n0 + r) * QKVC;
            uint4 kq = *(const uint4*)(rowp + CH + c * 8);
            uint4 vq = *(const uint4*)(rowp + 2 * CH + c * 8);
            *(uint4*)((char*)ks + r * 128 + ((c ^ (r & 7)) << 4)) = kq;
            *(uint4*)((char*)vs + r * 128 + ((c ^ (r & 7)) << 4)) = vq;
        }
        __syncthreads();

        #pragma unroll
        for (int ksi = 0; ksi < 2; ksi++) {
            uint32_t af[4], bf[8][2];
            {
                int nr = ksi * 16 + a_nrow;
                uint32_t addr = kb + nr * 128 + (((a_chunk ^ (nr & 7))) << 4);
                asm volatile(
                    "ldmatrix.sync.aligned.m8n8.x4.trans.shared.b16 {%0,%1,%2,%3}, [%4];"
                    : "=r"(af[0]), "=r"(af[1]), "=r"(af[2]), "=r"(af[3])
                    : "r"(addr));
            }
            #pragma unroll
            for (int nip = 0; nip < 4; nip++) {
                int kk = ksi * 16 + b_krow;
                int e = nip * 16 + b_eoff;
                int c = e >> 3;
                uint32_t addr = vb + kk * 128 + (((c ^ (kk & 7))) << 4);
                asm volatile(
                    "ldmatrix.sync.aligned.m8n8.x4.trans.shared.b16 {%0,%1,%2,%3}, [%4];"
                    : "=r"(bf[2 * nip][0]), "=r"(bf[2 * nip][1]),
                      "=r"(bf[2 * nip + 1][0]), "=r"(bf[2 * nip + 1][1])
                    : "r"(addr));
            }
            #pragma unroll
            for (int ni = 0; ni < 8; ni++)
                MMA16816(acc[ni], af, bf[ni][0], bf[ni][1]);
        }

        #pragma unroll
        for (int rr = 0; rr < 16; rr++) {
            int row = srow0 + rr;
            uint32_t a = kb + row * 128 + ((((scol >> 3) ^ (row & 7))) << 4) + s_in;
            __half hv;
            asm volatile("ld.shared.b16 %0, [%1];" : "=h"(*(short*)&hv) : "r"(a));
            ssum += __half2float(hv);
        }
        __syncthreads();
    }

    const int g = lane >> 2, tig = lane & 3;
    float* kvp = g_kvp + ((size_t)chunk * BH + bh) * HD * HD;
    #pragma unroll
    for (int hh = 0; hh < 2; hh++) {
        const int dr = d0 + g + hh * 8;
        #pragma unroll
        for (int ni = 0; ni < 8; ni++) {
            const int e = ni * 8 + 2 * tig;
            *(float2*)(kvp + dr * HD + e) =
                make_float2(acc[ni][hh * 2 + 0], acc[ni][hh * 2 + 1]);
        }
    }
    red[tid >> 6][scol] = ssum;
    __syncthreads();
    if (tid < HD)
        g_sumkp[((size_t)chunk * BH + bh) * HD + tid] = red[0][tid] + red[1][tid];
}

__global__ __launch_bounds__(256)
void kv_reduce_kernel()
{
    const int bh = blockIdx.x;
    const int tid = threadIdx.x;
    for (int i = tid; i < HD * HD; i += 256) {
        float s = 0.f;
        #pragma unroll
        for (int c = 0; c < KVCHUNKS; c++)
            s += g_kvp[((size_t)c * BH + bh) * HD * HD + i];
        g_kvh[(size_t)bh * HD * HD + i] = __float2half_rn(s);
    }
    if (tid < HD) {
        float s = 0.f;
        #pragma unroll
        for (int c = 0; c < KVCHUNKS; c++)
            s += g_sumkp[((size_t)c * BH + bh) * HD + tid];
        g_sumk[(size_t)bh * HD + tid] = s;
    }
}

// ================= y via tensor cores: y = (q @ kv) / (q . sumk) ===========
__global__ __launch_bounds__(128)
void y_mma_kernel()
{
    __shared__ __align__(16) __half qs[128 * 64];
    __shared__ __align__(16) __half kvs[64 * 64];
    __shared__ float sumkS[HD];
    __shared__ float denomS[128];

    const int tid  = threadIdx.x;
    const int lane = tid & 31;
    const int warp = tid >> 5;
    const int bh   = blockIdx.y;
    const int b    = bh / HEADS, h = bh % HEADS;
    const int n0   = blockIdx.x * 128;

    const __half* qg = g_qkvh + ((size_t)b * SEQ + n0) * QKVC + h * HD;

    #pragma unroll
    for (int it = 0; it < 8; it++) {
        int id = tid + it * 128;
        int r = id >> 3, c = id & 7;
        uint4 o = *(const uint4*)(qg + (size_t)r * QKVC + c * 8);
        *(uint4*)((char*)qs + r * 128 + (((c ^ (r & 7))) << 4)) = o;
    }
    const __half* kvg = g_kvh + (size_t)bh * HD * HD;
    #pragma unroll
    for (int it = 0; it < 4; it++) {
        int id = tid + it * 128;
        int d = id >> 3, c = id & 7;
        uint4 o = *(const uint4*)(kvg + d * HD + c * 8);
        *(uint4*)((char*)kvs + d * 128 + (((c ^ (d & 7))) << 4)) = o;
    }
    if (tid < HD) sumkS[tid] = g_sumk[(size_t)bh * HD + tid];
    __syncthreads();

    {
        const __half* qr = qg + (size_t)tid * QKVC;
        float s = 0.f;
        #pragma unroll
        for (int d = 0; d < HD; d += 8) {
            uint4 v = *(const uint4*)(qr + d);
            const __half2* hp = (const __half2*)&v;
            #pragma unroll
            for (int j = 0; j < 4; j++) {
                float2 f = __half22float2(hp[j]);
                s += f.x * sumkS[d + 2 * j] + f.y * sumkS[d + 2 * j + 1];
            }
        }
        denomS[tid] = 1.0f / s;
    }

    const uint32_t qb = smem_u32(qs);
    const uint32_t kb = smem_u32(kvs);

    float acc[2][8][4];
    #pragma unroll
    for (int i = 0; i < 2; i++)
        #pragma unroll
        for (int j = 0; j < 8; j++)
            #pragma unroll
            for (int l = 0; l < 4; l++) acc[i][j][l] = 0.f;

    #pragma unroll
    for (int ks = 0; ks < 4; ks++) {
        uint32_t af[2][4], bf[8][2];
        #pragma unroll
        for (int mi = 0; mi < 2; mi++) {
            int r = warp * 32 + mi * 16 + (lane & 15);
            int k = ks * 16 + ((lane >> 4) << 3);
            int c = k >> 3;
            uint32_t addr = qb + r * 128 + (((c ^ (r & 7))) << 4);
            asm volatile(
                "ldmatrix.sync.aligned.m8n8.x4.shared.b16 {%0,%1,%2,%3}, [%4];"
                : "=r"(af[mi][0]), "=r"(af[mi][1]), "=r"(af[mi][2]), "=r"(af[mi][3])
                : "r"(addr));
        }
        #pragma unroll
        for (int nip = 0; nip < 4; nip++) {
            int k = ks * 16 + (lane & 15);
            int n = nip * 16 + ((lane >> 4) << 3);
            int c = n >> 3;
            uint32_t addr = kb + k * 128 + (((c ^ (k & 7))) << 4);
            asm volatile(
                "ldmatrix.sync.aligned.m8n8.x4.trans.shared.b16 {%0,%1,%2,%3}, [%4];"
                : "=r"(bf[2 * nip][0]), "=r"(bf[2 * nip][1]),
                  "=r"(bf[2 * nip + 1][0]), "=r"(bf[2 * nip + 1][1])
                : "r"(addr));
        }
        #pragma unroll
        for (int mi = 0; mi < 2; mi++)
            #pragma unroll
            for (int ni = 0; ni < 8; ni++)
                MMA16816(acc[mi][ni], af[mi], bf[ni][0], bf[ni][1]);
    }

    __syncwarp();

    const int g = lane >> 2, tig = lane & 3;
    #pragma unroll
    for (int mi = 0; mi < 2; mi++) {
        #pragma unroll
        for (int hh = 0; hh < 2; hh++) {
            const int rl = warp * 32 + mi * 16 + g + hh * 8;
            const float inv = denomS[rl];
            __half* yrow = g_yh + ((size_t)b * SEQ + n0 + rl) * CH + h * HD;
            #pragma unroll
            for (int ni = 0; ni < 8; ni++) {
                const int col = ni * 8 + 2 * tig;
                __half2 p = __floats2half2_rn(acc[mi][ni][hh * 2 + 0] * inv,
                                              acc[mi][ni][hh * 2 + 1] * inv);
                *(__half2*)(yrow + col) = p;
            }
        }
    }
}

// ---------------------------------------------------------------------------
extern "C" void kernel_launch(void* const* d_in, const int* in_sizes, int n_in,
                              void* d_out, int out_size)
{
    const float* x      = (const float*)d_in[0];
    const float* w_qkv  = (const float*)d_in[1];
    const float* w_proj = (const float*)d_in[2];
    const float* b_proj = (const float*)d_in[3];
    float* out = (float*)d_out;

    __half *qkvh_p, *xh_p, *wqkvh_p, *wprojh_p, *yh_p;
    cudaGetSymbolAddress((void**)&qkvh_p,   g_qkvh);
    cudaGetSymbolAddress((void**)&xh_p,     g_xh);
    cudaGetSymbolAddress((void**)&wqkvh_p,  g_wqkvh);
    cudaGetSymbolAddress((void**)&wprojh_p, g_wprojh);
    cudaGetSymbolAddress((void**)&yh_p,     g_yh);

    cudaFuncSetAttribute(hgemm<1>, cudaFuncAttributeMaxDynamicSharedMemorySize, HG_SMEM);
    cudaFuncSetAttribute(hgemm<2>, cudaFuncAttributeMaxDynamicSharedMemorySize, HG_SMEM);

    // 0) fused fp32 -> fp16 conversion for x, w_qkv, w_proj
    cvt_all_kernel<<<(N8X + N8W + N8P) / 256, 256>>>(
        (const float4*)x, (const float4*)w_qkv, (const float4*)w_proj);

    // 1) qkv = x @ w_qkv (fp16 TC), elu+1 fused, fp16 out
    {
        dim3 grid(QKVC / 128, ROWS / 128);
        hgemm<1><<<grid, 128, HG_SMEM>>>(xh_p, wqkvh_p, nullptr, qkvh_p, QKVC, CH);
    }
    // 2) kv outer product on tensor cores (seq-split) + reduce
    {
        dim3 grid(BH, KVCHUNKS);
        kv_mma_kernel<<<grid, 128>>>();
        kv_reduce_kernel<<<BH, 256>>>();
    }
    // 3) y = (q @ kv) / (q . sumk) on tensor cores, fp16 out
    {
        dim3 grid(SEQ / 128, BH);
        y_mma_kernel<<<grid, 128>>>();
    }
    // 4) out = y @ w_proj + b_proj (fp16 TC, fp32 out)
    {
        dim3 grid(CH / 128, ROWS / 128);
        hgemm<2><<<grid, 128, HG_SMEM>>>(yh_p, wprojh_p, b_proj, out, CH, CH);
    }
}